// round 12
// baseline (speedup 1.0000x reference)
#include <cuda_runtime.h>
#include <math.h>

#define LMAX 8192
#define HH 4

__device__ float g_nx[LMAX * 512];    // tf32-rounded
__device__ float g_uvqk[LMAX * 1024]; // tf32-rounded
__device__ float g_attn[LMAX * 256];  // fp32
__device__ float g_y[LMAX * 256];     // tf32-rounded

__device__ __forceinline__ float silu_(float z) {
    return z / (1.0f + __expf(-z));
}

__device__ __forceinline__ float tanh_(float x) {
    float r;
    asm("tanh.approx.f32 %0, %1;" : "=f"(r) : "f"(x));
    return r;
}

__device__ __forceinline__ unsigned tf32_(float f) {
    unsigned r;
    asm("cvt.rna.tf32.f32 %0, %1;" : "=r"(r) : "f"(f));
    return r;
}

__device__ __forceinline__ float tf32f_(float f) {
    return __uint_as_float(tf32_(f));
}

__device__ __forceinline__ void mma8(float* d, unsigned a0, unsigned a1, unsigned a2,
                                     unsigned a3, unsigned b0, unsigned b1) {
    asm volatile(
        "mma.sync.aligned.m16n8k8.row.col.f32.tf32.tf32.f32 "
        "{%0,%1,%2,%3}, {%4,%5,%6,%7}, {%8,%9}, {%0,%1,%2,%3};\n"
        : "+f"(d[0]), "+f"(d[1]), "+f"(d[2]), "+f"(d[3])
        : "r"(a0), "r"(a1), "r"(a2), "r"(a3), "r"(b0), "r"(b1));
}

__device__ __forceinline__ void cpa16(void* s, const void* g) {
    unsigned sa = (unsigned)__cvta_generic_to_shared(s);
    asm volatile("cp.async.cg.shared.global [%0], [%1], 16;" ::"r"(sa), "l"(g));
}
__device__ __forceinline__ void cpa16z(void* s, const void* g, bool ok) {
    unsigned sa = (unsigned)__cvta_generic_to_shared(s);
    int sz = ok ? 16 : 0;
    asm volatile("cp.async.cg.shared.global [%0], [%1], 16, %2;" ::"r"(sa), "l"(g),
                 "r"(sz));
}
#define CP_COMMIT asm volatile("cp.async.commit_group;")
#define CP_WAIT0 asm volatile("cp.async.wait_group 0;")
#define CP_WAIT1 asm volatile("cp.async.wait_group 1;")

// ---------------- input layernorm: warp per row, (L,512) -> g_nx ----------------
__global__ __launch_bounds__(256) void k_ln_in(const float* __restrict__ x,
                                               const float* __restrict__ w,
                                               const float* __restrict__ b, int L) {
    int row = blockIdx.x * 8 + (threadIdx.x >> 5);
    if (row >= L) return;
    int lane = threadIdx.x & 31;
    const float4* xr = (const float4*)(x + (size_t)row * 512);
    float4 v[4];
    float s = 0.f, ss = 0.f;
#pragma unroll
    for (int i = 0; i < 4; i++) {
        v[i] = xr[lane + 32 * i];
        s += v[i].x + v[i].y + v[i].z + v[i].w;
        ss += v[i].x * v[i].x + v[i].y * v[i].y + v[i].z * v[i].z + v[i].w * v[i].w;
    }
#pragma unroll
    for (int o = 16; o; o >>= 1) {
        s += __shfl_xor_sync(0xffffffffu, s, o);
        ss += __shfl_xor_sync(0xffffffffu, ss, o);
    }
    float mean = s * (1.0f / 512.0f);
    float var = ss * (1.0f / 512.0f) - mean * mean;
    float r = rsqrtf(var + 1e-6f);
    float4* o = (float4*)(g_nx + (size_t)row * 512);
    const float4* wp = (const float4*)w;
    const float4* bp = (const float4*)b;
#pragma unroll
    for (int i = 0; i < 4; i++) {
        float4 wv = wp[lane + 32 * i], bv = bp[lane + 32 * i];
        float4 ov;
        ov.x = tf32f_((v[i].x - mean) * r * wv.x + bv.x);
        ov.y = tf32f_((v[i].y - mean) * r * wv.y + bv.y);
        ov.z = tf32f_((v[i].z - mean) * r * wv.z + bv.z);
        ov.w = tf32f_((v[i].w - mean) * r * wv.w + bv.w);
        o[lane + 32 * i] = ov;
    }
}

// ---------------- output layernorm: warp per row, g_attn (L,256) -> g_y ----------------
__global__ __launch_bounds__(256) void k_ln_out(const float* __restrict__ w,
                                                const float* __restrict__ b, int L) {
    int row = blockIdx.x * 8 + (threadIdx.x >> 5);
    if (row >= L) return;
    int lane = threadIdx.x & 31;
    const float4* xr = (const float4*)(g_attn + (size_t)row * 256);
    float4 v[2];
    float s = 0.f, ss = 0.f;
#pragma unroll
    for (int i = 0; i < 2; i++) {
        v[i] = xr[lane + 32 * i];
        s += v[i].x + v[i].y + v[i].z + v[i].w;
        ss += v[i].x * v[i].x + v[i].y * v[i].y + v[i].z * v[i].z + v[i].w * v[i].w;
    }
#pragma unroll
    for (int o = 16; o; o >>= 1) {
        s += __shfl_xor_sync(0xffffffffu, s, o);
        ss += __shfl_xor_sync(0xffffffffu, ss, o);
    }
    float mean = s * (1.0f / 256.0f);
    float var = ss * (1.0f / 256.0f) - mean * mean;
    float r = rsqrtf(var + 1e-6f);
    float4* o = (float4*)(g_y + (size_t)row * 256);
    const float4* wp = (const float4*)w;
    const float4* bp = (const float4*)b;
#pragma unroll
    for (int i = 0; i < 2; i++) {
        float4 wv = wp[lane + 32 * i], bv = bp[lane + 32 * i];
        float4 ov;
        ov.x = tf32f_((v[i].x - mean) * r * wv.x + bv.x);
        ov.y = tf32f_((v[i].y - mean) * r * wv.y + bv.y);
        ov.z = tf32f_((v[i].z - mean) * r * wv.z + bv.z);
        ov.w = tf32f_((v[i].w - mean) * r * wv.w + bv.w);
        o[lane + 32 * i] = ov;
    }
}

// ---------------- GEMM core constants ----------------
#define AS_PITCH 36
#define BS_PITCH 136
#define AS_WORDS (128 * AS_PITCH)
#define BS_WORDS (32 * BS_PITCH)
#define STG_WORDS (AS_WORDS + BS_WORDS)
#define GEMM_SMEM ((3 * STG_WORDS) * 4)

// ---------------- GEMM1: g_uvqk = silu(g_nx @ W(512x1024) + bias), tf32-rounded ----------------
__global__ __launch_bounds__(256) void k_gemm1_tc(const float* __restrict__ W,
                                                  const float* __restrict__ bias, int L) {
    extern __shared__ unsigned smu[];
    int tid = threadIdx.x, lane = tid & 31, wid = tid >> 5;
    int wm = wid >> 2, wn = wid & 3;
    int l4 = lane >> 2, l3 = lane & 3;
    int row0 = blockIdx.y * 128, col0 = blockIdx.x * 128;

    float acc[4][4][4];
#pragma unroll
    for (int i = 0; i < 4; i++)
#pragma unroll
        for (int j = 0; j < 4; j++)
#pragma unroll
            for (int q = 0; q < 4; q++) acc[i][j][q] = 0.f;

    int ar_r = tid >> 3, ar_c = (tid & 7) * 4;
    int br_r = tid >> 5, br_c = (tid & 31) * 4;

    auto prefetch = [&](int k0, int st) {
        unsigned* As = smu + st * STG_WORDS;
        unsigned* Bs = As + AS_WORDS;
#pragma unroll
        for (int p = 0; p < 4; p++) {
            int gr = min(row0 + ar_r + p * 32, L - 1);
            cpa16(&As[(ar_r + p * 32) * AS_PITCH + ar_c],
                  g_nx + (size_t)gr * 512 + k0 + ar_c);
            cpa16(&Bs[(br_r + p * 8) * BS_PITCH + br_c],
                  W + (size_t)(k0 + br_r + p * 8) * 1024 + col0 + br_c);
        }
        CP_COMMIT;
    };
    auto compute = [&](int st) {
        unsigned* As = smu + st * STG_WORDS;
        unsigned* Bs = As + AS_WORDS;
#pragma unroll
        for (int kk = 0; kk < 32; kk += 8) {
            unsigned b0[4], b1[4];
#pragma unroll
            for (int nt = 0; nt < 4; nt++) {
                int bc = wn * 32 + nt * 8 + l4;
                b0[nt] = Bs[(kk + l3) * BS_PITCH + bc];
                b1[nt] = Bs[(kk + l3 + 4) * BS_PITCH + bc];
            }
#pragma unroll
            for (int mt = 0; mt < 4; mt++) {
                int ar = wm * 64 + mt * 16 + l4;
                unsigned a0 = As[ar * AS_PITCH + kk + l3];
                unsigned a1 = As[(ar + 8) * AS_PITCH + kk + l3];
                unsigned a2 = As[ar * AS_PITCH + kk + l3 + 4];
                unsigned a3 = As[(ar + 8) * AS_PITCH + kk + l3 + 4];
#pragma unroll
                for (int nt = 0; nt < 4; nt++)
                    mma8(acc[mt][nt], a0, a1, a2, a3, b0[nt], b1[nt]);
            }
        }
    };

    prefetch(0, 0);
    prefetch(32, 1);
    int cur = 0;
    for (int k0 = 0; k0 < 512; k0 += 32) {
        if (k0 + 32 < 512) { CP_WAIT1; } else { CP_WAIT0; }
        __syncthreads();
        if (k0 + 64 < 512) {
            int st = cur + 2;
            if (st >= 3) st -= 3;
            prefetch(k0 + 64, st);
        }
        compute(cur);
        if (++cur == 3) cur = 0;
    }

#pragma unroll
    for (int mt = 0; mt < 4; mt++)
#pragma unroll
        for (int nt = 0; nt < 4; nt++) {
            int r = row0 + wm * 64 + mt * 16 + l4;
            int c = col0 + wn * 32 + nt * 8 + l3 * 2;
            float2 bb = *(const float2*)(bias + c);
            if (r < L) {
                float2 o;
                o.x = tf32f_(silu_(acc[mt][nt][0] + bb.x));
                o.y = tf32f_(silu_(acc[mt][nt][1] + bb.y));
                *(float2*)(g_uvqk + (size_t)r * 1024 + c) = o;
            }
            if (r + 8 < L) {
                float2 o;
                o.x = tf32f_(silu_(acc[mt][nt][2] + bb.x));
                o.y = tf32f_(silu_(acc[mt][nt][3] + bb.y));
                *(float2*)(g_uvqk + (size_t)(r + 8) * 1024 + c) = o;
            }
        }
}

// ---------------- GEMM2: out = x + [u|x|y] @ Wout(1024x512) ----------------
__global__ __launch_bounds__(256) void k_gemm2_tc(const float* __restrict__ x,
                                                  const float* __restrict__ Wout, int L,
                                                  float* __restrict__ out) {
    extern __shared__ unsigned smu[];
    int tid = threadIdx.x, lane = tid & 31, wid = tid >> 5;
    int wm = wid >> 2, wn = wid & 3;
    int l4 = lane >> 2, l3 = lane & 3;
    int row0 = blockIdx.y * 128, col0 = blockIdx.x * 128;

    float acc[4][4][4];
#pragma unroll
    for (int i = 0; i < 4; i++)
#pragma unroll
        for (int j = 0; j < 4; j++)
#pragma unroll
            for (int q = 0; q < 4; q++) acc[i][j][q] = 0.f;

    int ar_r = tid >> 3, ar_c = (tid & 7) * 4;
    int br_r = tid >> 5, br_c = (tid & 31) * 4;

    auto prefetch = [&](int k0, int st) {
        unsigned* As = smu + st * STG_WORDS;
        unsigned* Bs = As + AS_WORDS;
        int j = k0 + ar_c;
        const float* base;
        int pitch;
        if (j < 256) { base = g_uvqk + j; pitch = 1024; }
        else if (j < 768) { base = x + (j - 256); pitch = 512; }
        else { base = g_y + (j - 768); pitch = 256; }
#pragma unroll
        for (int p = 0; p < 4; p++) {
            int gr = min(row0 + ar_r + p * 32, L - 1);
            cpa16(&As[(ar_r + p * 32) * AS_PITCH + ar_c], base + (size_t)gr * pitch);
            cpa16(&Bs[(br_r + p * 8) * BS_PITCH + br_c],
                  Wout + (size_t)(k0 + br_r + p * 8) * 512 + col0 + br_c);
        }
        CP_COMMIT;
    };
    auto compute = [&](int st) {
        unsigned* As = smu + st * STG_WORDS;
        unsigned* Bs = As + AS_WORDS;
#pragma unroll
        for (int kk = 0; kk < 32; kk += 8) {
            unsigned b0[4], b1[4];
#pragma unroll
            for (int nt = 0; nt < 4; nt++) {
                int bc = wn * 32 + nt * 8 + l4;
                b0[nt] = Bs[(kk + l3) * BS_PITCH + bc];
                b1[nt] = Bs[(kk + l3 + 4) * BS_PITCH + bc];
            }
#pragma unroll
            for (int mt = 0; mt < 4; mt++) {
                int ar = wm * 64 + mt * 16 + l4;
                unsigned a0 = As[ar * AS_PITCH + kk + l3];
                unsigned a1 = As[(ar + 8) * AS_PITCH + kk + l3];
                unsigned a2 = As[ar * AS_PITCH + kk + l3 + 4];
                unsigned a3 = As[(ar + 8) * AS_PITCH + kk + l3 + 4];
#pragma unroll
                for (int nt = 0; nt < 4; nt++)
                    mma8(acc[mt][nt], a0, a1, a2, a3, b0[nt], b1[nt]);
            }
        }
    };

    prefetch(0, 0);
    prefetch(32, 1);
    int cur = 0;
    for (int k0 = 0; k0 < 1024; k0 += 32) {
        if (k0 + 32 < 1024) { CP_WAIT1; } else { CP_WAIT0; }
        __syncthreads();
        if (k0 + 64 < 1024) {
            int st = cur + 2;
            if (st >= 3) st -= 3;
            prefetch(k0 + 64, st);
        }
        compute(cur);
        if (++cur == 3) cur = 0;
    }

#pragma unroll
    for (int mt = 0; mt < 4; mt++)
#pragma unroll
        for (int nt = 0; nt < 4; nt++) {
            int r = row0 + wm * 64 + mt * 16 + l4;
            int c = col0 + wn * 32 + nt * 8 + l3 * 2;
            if (r < L) {
                float2 xv = *(const float2*)(x + (size_t)r * 512 + c);
                float2 o;
                o.x = xv.x + acc[mt][nt][0];
                o.y = xv.y + acc[mt][nt][1];
                *(float2*)(out + (size_t)r * 512 + c) = o;
            }
            if (r + 8 < L) {
                float2 xv = *(const float2*)(x + (size_t)(r + 8) * 512 + c);
                float2 o;
                o.x = xv.x + acc[mt][nt][2];
                o.y = xv.y + acc[mt][nt][3];
                *(float2*)(out + (size_t)(r + 8) * 512 + c) = o;
            }
        }
}

// ---------------- attention (tensor core tf32, cp.async double-buffered K/V) ----------------
#define ATT_QS 0
#define ATT_KS 4352
#define ATT_KS_W 4352
#define ATT_VS 13056
#define ATT_VS_W 4608
#define ATT_SMEM ((13056 + 2 * 4608) * 4)

__global__ __launch_bounds__(256) void k_attn_tc(const int* __restrict__ lengths,
                                                 const int* __restrict__ offsets,
                                                 const int* __restrict__ ntargets,
                                                 const int* __restrict__ msl, int TPB) {
    extern __shared__ unsigned smu[];
    unsigned(*QSs)[68] = (unsigned(*)[68])(smu + ATT_QS);
    float(*Ss)[68] = (float(*)[68])(smu + ATT_QS);  // alias: Q consumed before S written

    int h = blockIdx.y;
    int b = blockIdx.x / TPB;
    int t = TPB - 1 - (blockIdx.x % TPB);  // long blocks launch first
    int len = lengths[b];
    int q0 = t * 64;
    if (q0 >= len) return;
    int off = offsets[b];
    int lim = len - ntargets[b];
    float invN = 1.0f / (float)msl[0];
    float c1 = 0.125f * invN;  // z*invN = s*c1

    int tid = threadIdx.x, lane = tid & 31, wid = tid >> 5;
    int wm = wid >> 1, wn = wid & 1;
    int l4 = lane >> 2, l3 = lane & 3;
    int lr = tid >> 2, lc0 = (tid & 3) * 16;

    const uint4 zero4 = make_uint4(0u, 0u, 0u, 0u);

    auto prefetchKV = [&](int m0, int st) {
        int m = m0 + lr;
        bool ok = m < len;
        const float* kp =
            g_uvqk + (size_t)(off + min(m, len - 1)) * 1024 + 768 + h * 64 + lc0;
        const float* vp = kp - 512;  // v segment at 256
        unsigned* Kst = smu + ATT_KS + st * ATT_KS_W;
        unsigned* Vst = smu + ATT_VS + st * ATT_VS_W;
#pragma unroll
        for (int i = 0; i < 4; i++) {
            cpa16z(&Kst[lr * 68 + lc0 + i * 4], kp + i * 4, ok);
            cpa16z(&Vst[lr * 72 + lc0 + i * 4], vp + i * 4, ok);
        }
        CP_COMMIT;
    };

    prefetchKV(0, 0);
    {
        int n = q0 + lr;
        const uint4* qp = (const uint4*)(g_uvqk + (size_t)(off + min(n, len - 1)) * 1024 +
                                         512 + h * 64 + lc0);
        bool ok = n < len;
#pragma unroll
        for (int i = 0; i < 4; i++)
            *(uint4*)&QSs[lr][lc0 + i * 4] = ok ? qp[i] : zero4;
    }
    __syncthreads();

    unsigned qf[8][4];
#pragma unroll
    for (int ks = 0; ks < 8; ks++) {
        qf[ks][0] = QSs[wm * 16 + l4][ks * 8 + l3];
        qf[ks][1] = QSs[wm * 16 + l4 + 8][ks * 8 + l3];
        qf[ks][2] = QSs[wm * 16 + l4][ks * 8 + l3 + 4];
        qf[ks][3] = QSs[wm * 16 + l4 + 8][ks * 8 + l3 + 4];
    }

    float oacc[4][4];
#pragma unroll
    for (int i = 0; i < 4; i++)
#pragma unroll
        for (int j = 0; j < 4; j++) oacc[i][j] = 0.f;

    int nIter = q0 / 64 + 1;
    int cur = 0;
    for (int it = 0; it < nIter; it++) {
        int m0 = it * 64;
        CP_WAIT0;
        __syncthreads();
        if (it + 1 < nIter) prefetchKV(m0 + 64, cur ^ 1);

        const unsigned* Kst = smu + ATT_KS + cur * ATT_KS_W;
        const unsigned* Vst = smu + ATT_VS + cur * ATT_VS_W;

        // ---- QK^T ----
        float sacc[4][4];
#pragma unroll
        for (int i = 0; i < 4; i++)
#pragma unroll
            for (int j = 0; j < 4; j++) sacc[i][j] = 0.f;
#pragma unroll
        for (int ks = 0; ks < 8; ks++) {
            unsigned b0[4], b1[4];
#pragma unroll
            for (int nt = 0; nt < 4; nt++) {
                int mr = wn * 32 + nt * 8 + l4;
                b0[nt] = Kst[mr * 68 + ks * 8 + l3];
                b1[nt] = Kst[mr * 68 + ks * 8 + l3 + 4];
            }
#pragma unroll
            for (int nt = 0; nt < 4; nt++)
                mma8(sacc[nt], qf[ks][0], qf[ks][1], qf[ks][2], qf[ks][3], b0[nt], b1[nt]);
        }

        // ---- silu (tanh form) + mask, store S ----
        bool easy = (m0 + 64 <= q0) && (q0 + 64 <= lim);
        if (easy) {
#pragma unroll
            for (int nt = 0; nt < 4; nt++) {
#pragma unroll
                for (int q = 0; q < 4; q++) {
                    float s = sacc[nt][q];
                    float tg = tanh_(s * 0.0625f);
                    sacc[nt][q] = (s * c1) * fmaf(0.5f, tg, 0.5f);
                }
                int sr = wm * 16 + l4;
                int sc = wn * 32 + nt * 8 + 2 * l3;
                *(float2*)&Ss[sr][sc] = make_float2(sacc[nt][0], sacc[nt][1]);
                *(float2*)&Ss[sr + 8][sc] = make_float2(sacc[nt][2], sacc[nt][3]);
            }
        } else {
            int n_lo = q0 + wm * 16 + l4;
            int n_hi = n_lo + 8;
            int idn_lo = min(n_lo, lim), idn_hi = min(n_hi, lim);
            bool nok_lo = n_lo < len, nok_hi = n_hi < len;
#pragma unroll
            for (int nt = 0; nt < 4; nt++) {
                int m_ = m0 + wn * 32 + nt * 8 + 2 * l3;
#pragma unroll
                for (int jj = 0; jj < 2; jj++) {
                    int m = m_ + jj;
                    int idm = min(m, lim);
                    bool mok = m < len;
                    float s0 = sacc[nt][jj];
                    float w0 = (s0 * c1) * fmaf(0.5f, tanh_(s0 * 0.0625f), 0.5f);
                    bool ok0 = mok && nok_lo && ((idn_lo > idm) || (n_lo == m));
                    sacc[nt][jj] = ok0 ? w0 : 0.f;
                    float s1 = sacc[nt][jj + 2];
                    float w1 = (s1 * c1) * fmaf(0.5f, tanh_(s1 * 0.0625f), 0.5f);
                    bool ok1 = mok && nok_hi && ((idn_hi > idm) || (n_hi == m));
                    sacc[nt][jj + 2] = ok1 ? w1 : 0.f;
                }
                int sr = wm * 16 + l4;
                int sc = wn * 32 + nt * 8 + 2 * l3;
                *(float2*)&Ss[sr][sc] = make_float2(sacc[nt][0], sacc[nt][1]);
                *(float2*)&Ss[sr + 8][sc] = make_float2(sacc[nt][2], sacc[nt][3]);
            }
        }
        __syncthreads();

        // ---- PV ----
#pragma unroll
        for (int km = 0; km < 8; km++) {
            unsigned a0 = __float_as_uint(Ss[wm * 16 + l4][km * 8 + l3]);
            unsigned a1 = __float_as_uint(Ss[wm * 16 + l4 + 8][km * 8 + l3]);
            unsigned a2 = __float_as_uint(Ss[wm * 16 + l4][km * 8 + l3 + 4]);
            unsigned a3 = __float_as_uint(Ss[wm * 16 + l4 + 8][km * 8 + l3 + 4]);
#pragma unroll
            for (int nt = 0; nt < 4; nt++) {
                unsigned b0 = Vst[(km * 8 + l3) * 72 + wn * 32 + nt * 8 + l4];
                unsigned b1 = Vst[(km * 8 + l3 + 4) * 72 + wn * 32 + nt * 8 + l4];
                mma8(oacc[nt], a0, a1, a2, a3, b0, b1);
            }
        }
        cur ^= 1;
    }

#pragma unroll
    for (int nt = 0; nt < 4; nt++) {
        int col = h * 64 + wn * 32 + nt * 8 + 2 * l3;
        int n = q0 + wm * 16 + l4;
        if (n < len)
            *(float2*)&g_attn[(size_t)(off + n) * 256 + col] =
                make_float2(oacc[nt][0], oacc[nt][1]);
        if (n + 8 < len)
            *(float2*)&g_attn[(size_t)(off + n + 8) * 256 + col] =
                make_float2(oacc[nt][2], oacc[nt][3]);
    }
}

extern "C" void kernel_launch(void* const* d_in, const int* in_sizes, int n_in,
                              void* d_out, int out_size) {
    const float* x = (const float*)d_in[0];
    const int* xl = (const int*)d_in[1];
    const int* xo = (const int*)d_in[2];
    const int* msl = (const int*)d_in[3];
    const int* nt = (const int*)d_in[4];
    const float* Wu = (const float*)d_in[5];
    const float* bu = (const float*)d_in[6];
    const float* inw = (const float*)d_in[7];
    const float* inb = (const float*)d_in[8];
    const float* onw = (const float*)d_in[9];
    const float* onb = (const float*)d_in[10];
    const float* Wo = (const float*)d_in[11];
    float* out = (float*)d_out;

    int L = in_sizes[0] / 512;
    int B = in_sizes[1];

    static bool attr_set = false;
    if (!attr_set) {
        cudaFuncSetAttribute(k_attn_tc, cudaFuncAttributeMaxDynamicSharedMemorySize,
                             ATT_SMEM);
        cudaFuncSetAttribute(k_gemm1_tc, cudaFuncAttributeMaxDynamicSharedMemorySize,
                             GEMM_SMEM);
        cudaFuncSetAttribute(k_gemm2_tc, cudaFuncAttributeMaxDynamicSharedMemorySize,
                             GEMM_SMEM);
        attr_set = true;
    }

    k_ln_in<<<(L + 7) / 8, 256>>>(x, inw, inb, L);

    dim3 g1(1024 / 128, (L + 127) / 128);
    k_gemm1_tc<<<g1, 256, GEMM_SMEM>>>(Wu, bu, L);

    int TPB = (L + 63) / 64;
    dim3 ga(B * TPB, HH);
    k_attn_tc<<<ga, 256, ATT_SMEM>>>(xl, xo, nt, msl, TPB);

    k_ln_out<<<(L + 7) / 8, 256>>>(onw, onb, L);

    dim3 g2(512 / 128, (L + 127) / 128);
    k_gemm2_tc<<<g2, 256, GEMM_SMEM>>>(x, Wo, L, out);
}

// round 13
// speedup vs baseline: 1.0075x; 1.0075x over previous
#include <cuda_runtime.h>
#include <math.h>

#define LMAX 8192
#define HH 4

__device__ float g_nx[LMAX * 512];    // tf32-rounded
__device__ float g_uvqk[LMAX * 1024]; // tf32-rounded
__device__ float g_attn[LMAX * 256];  // fp32
__device__ float g_y[LMAX * 256];     // tf32-rounded

__device__ __forceinline__ float silu_(float z) {
    return z / (1.0f + __expf(-z));
}

__device__ __forceinline__ float tanh_(float x) {
    float r;
    asm("tanh.approx.f32 %0, %1;" : "=f"(r) : "f"(x));
    return r;
}

__device__ __forceinline__ unsigned tf32_(float f) {
    unsigned r;
    asm("cvt.rna.tf32.f32 %0, %1;" : "=r"(r) : "f"(f));
    return r;
}

__device__ __forceinline__ float tf32f_(float f) {
    return __uint_as_float(tf32_(f));
}

__device__ __forceinline__ void mma8(float* d, unsigned a0, unsigned a1, unsigned a2,
                                     unsigned a3, unsigned b0, unsigned b1) {
    asm volatile(
        "mma.sync.aligned.m16n8k8.row.col.f32.tf32.tf32.f32 "
        "{%0,%1,%2,%3}, {%4,%5,%6,%7}, {%8,%9}, {%0,%1,%2,%3};\n"
        : "+f"(d[0]), "+f"(d[1]), "+f"(d[2]), "+f"(d[3])
        : "r"(a0), "r"(a1), "r"(a2), "r"(a3), "r"(b0), "r"(b1));
}

__device__ __forceinline__ void cpa16(void* s, const void* g) {
    unsigned sa = (unsigned)__cvta_generic_to_shared(s);
    asm volatile("cp.async.cg.shared.global [%0], [%1], 16;" ::"r"(sa), "l"(g));
}
__device__ __forceinline__ void cpa16z(void* s, const void* g, bool ok) {
    unsigned sa = (unsigned)__cvta_generic_to_shared(s);
    int sz = ok ? 16 : 0;
    asm volatile("cp.async.cg.shared.global [%0], [%1], 16, %2;" ::"r"(sa), "l"(g),
                 "r"(sz));
}
#define CP_COMMIT asm volatile("cp.async.commit_group;")
#define CP_WAIT0 asm volatile("cp.async.wait_group 0;")

// ---------------- input layernorm: warp per row, (L,512) -> g_nx ----------------
__global__ __launch_bounds__(256) void k_ln_in(const float* __restrict__ x,
                                               const float* __restrict__ w,
                                               const float* __restrict__ b, int L) {
    int row = blockIdx.x * 8 + (threadIdx.x >> 5);
    if (row >= L) return;
    int lane = threadIdx.x & 31;
    const float4* xr = (const float4*)(x + (size_t)row * 512);
    float4 v[4];
    float s = 0.f, ss = 0.f;
#pragma unroll
    for (int i = 0; i < 4; i++) {
        v[i] = xr[lane + 32 * i];
        s += v[i].x + v[i].y + v[i].z + v[i].w;
        ss += v[i].x * v[i].x + v[i].y * v[i].y + v[i].z * v[i].z + v[i].w * v[i].w;
    }
#pragma unroll
    for (int o = 16; o; o >>= 1) {
        s += __shfl_xor_sync(0xffffffffu, s, o);
        ss += __shfl_xor_sync(0xffffffffu, ss, o);
    }
    float mean = s * (1.0f / 512.0f);
    float var = ss * (1.0f / 512.0f) - mean * mean;
    float r = rsqrtf(var + 1e-6f);
    float4* o = (float4*)(g_nx + (size_t)row * 512);
    const float4* wp = (const float4*)w;
    const float4* bp = (const float4*)b;
#pragma unroll
    for (int i = 0; i < 4; i++) {
        float4 wv = wp[lane + 32 * i], bv = bp[lane + 32 * i];
        float4 ov;
        ov.x = tf32f_((v[i].x - mean) * r * wv.x + bv.x);
        ov.y = tf32f_((v[i].y - mean) * r * wv.y + bv.y);
        ov.z = tf32f_((v[i].z - mean) * r * wv.z + bv.z);
        ov.w = tf32f_((v[i].w - mean) * r * wv.w + bv.w);
        o[lane + 32 * i] = ov;
    }
}

// ---------------- output layernorm: warp per row, g_attn (L,256) -> g_y ----------------
__global__ __launch_bounds__(256) void k_ln_out(const float* __restrict__ w,
                                                const float* __restrict__ b, int L) {
    int row = blockIdx.x * 8 + (threadIdx.x >> 5);
    if (row >= L) return;
    int lane = threadIdx.x & 31;
    const float4* xr = (const float4*)(g_attn + (size_t)row * 256);
    float4 v[2];
    float s = 0.f, ss = 0.f;
#pragma unroll
    for (int i = 0; i < 2; i++) {
        v[i] = xr[lane + 32 * i];
        s += v[i].x + v[i].y + v[i].z + v[i].w;
        ss += v[i].x * v[i].x + v[i].y * v[i].y + v[i].z * v[i].z + v[i].w * v[i].w;
    }
#pragma unroll
    for (int o = 16; o; o >>= 1) {
        s += __shfl_xor_sync(0xffffffffu, s, o);
        ss += __shfl_xor_sync(0xffffffffu, ss, o);
    }
    float mean = s * (1.0f / 256.0f);
    float var = ss * (1.0f / 256.0f) - mean * mean;
    float r = rsqrtf(var + 1e-6f);
    float4* o = (float4*)(g_y + (size_t)row * 256);
    const float4* wp = (const float4*)w;
    const float4* bp = (const float4*)b;
#pragma unroll
    for (int i = 0; i < 2; i++) {
        float4 wv = wp[lane + 32 * i], bv = bp[lane + 32 * i];
        float4 ov;
        ov.x = tf32f_((v[i].x - mean) * r * wv.x + bv.x);
        ov.y = tf32f_((v[i].y - mean) * r * wv.y + bv.y);
        ov.z = tf32f_((v[i].z - mean) * r * wv.z + bv.z);
        ov.w = tf32f_((v[i].w - mean) * r * wv.w + bv.w);
        o[lane + 32 * i] = ov;
    }
}

// ---------------- GEMM core constants (2-stage) ----------------
#define AS_PITCH 36
#define BS_PITCH 136
#define AS_WORDS (128 * AS_PITCH)
#define BS_WORDS (32 * BS_PITCH)
#define GEMM_SMEM ((2 * (AS_WORDS + BS_WORDS)) * 4)

#define GEMM_COMPUTE()                                                        \
    do {                                                                      \
        _Pragma("unroll") for (int kk = 0; kk < 32; kk += 8) {                \
            unsigned b0[4], b1[4];                                            \
            _Pragma("unroll") for (int nt = 0; nt < 4; nt++) {                \
                int bc = wn * 32 + nt * 8 + l4;                               \
                b0[nt] = Bs[(kk + l3) * BS_PITCH + bc];                       \
                b1[nt] = Bs[(kk + l3 + 4) * BS_PITCH + bc];                   \
            }                                                                 \
            _Pragma("unroll") for (int mt = 0; mt < 4; mt++) {                \
                int ar = wm * 64 + mt * 16 + l4;                              \
                unsigned a0 = As[ar * AS_PITCH + kk + l3];                    \
                unsigned a1 = As[(ar + 8) * AS_PITCH + kk + l3];              \
                unsigned a2 = As[ar * AS_PITCH + kk + l3 + 4];                \
                unsigned a3 = As[(ar + 8) * AS_PITCH + kk + l3 + 4];          \
                _Pragma("unroll") for (int nt = 0; nt < 4; nt++)              \
                    mma8(acc[mt][nt], a0, a1, a2, a3, b0[nt], b1[nt]);        \
            }                                                                 \
        }                                                                     \
    } while (0)

// ---------------- GEMM1: g_uvqk = silu(g_nx @ W(512x1024) + bias), tf32-rounded ----------------
__global__ __launch_bounds__(256) void k_gemm1_tc(const float* __restrict__ W,
                                                  const float* __restrict__ bias, int L) {
    extern __shared__ unsigned smu[];
    unsigned* AsB = smu;
    unsigned* BsB = smu + 2 * AS_WORDS;
    int tid = threadIdx.x, lane = tid & 31, wid = tid >> 5;
    int wm = wid >> 2, wn = wid & 3;
    int l4 = lane >> 2, l3 = lane & 3;
    int row0 = blockIdx.y * 128, col0 = blockIdx.x * 128;

    float acc[4][4][4];
#pragma unroll
    for (int i = 0; i < 4; i++)
#pragma unroll
        for (int j = 0; j < 4; j++)
#pragma unroll
            for (int q = 0; q < 4; q++) acc[i][j][q] = 0.f;

    int ar_r = tid >> 3, ar_c = (tid & 7) * 4;
    int br_r = tid >> 5, br_c = (tid & 31) * 4;

    auto prefetch = [&](int k0, int st) {
        unsigned* As = AsB + st * AS_WORDS;
        unsigned* Bs = BsB + st * BS_WORDS;
#pragma unroll
        for (int p = 0; p < 4; p++) {
            int gr = min(row0 + ar_r + p * 32, L - 1);
            cpa16(&As[(ar_r + p * 32) * AS_PITCH + ar_c],
                  g_nx + (size_t)gr * 512 + k0 + ar_c);
            cpa16(&Bs[(br_r + p * 8) * BS_PITCH + br_c],
                  W + (size_t)(k0 + br_r + p * 8) * 1024 + col0 + br_c);
        }
        CP_COMMIT;
    };

    prefetch(0, 0);
    CP_WAIT0;
    __syncthreads();
    int cur = 0;
    for (int k0 = 0; k0 < 512; k0 += 32) {
        if (k0 + 32 < 512) prefetch(k0 + 32, cur ^ 1);
        {
            unsigned* As = AsB + cur * AS_WORDS;
            unsigned* Bs = BsB + cur * BS_WORDS;
            GEMM_COMPUTE();
        }
        if (k0 + 32 < 512) {
            CP_WAIT0;
            __syncthreads();
            cur ^= 1;
        }
    }

#pragma unroll
    for (int mt = 0; mt < 4; mt++)
#pragma unroll
        for (int nt = 0; nt < 4; nt++) {
            int r = row0 + wm * 64 + mt * 16 + l4;
            int c = col0 + wn * 32 + nt * 8 + l3 * 2;
            float2 bb = *(const float2*)(bias + c);
            if (r < L) {
                float2 o;
                o.x = tf32f_(silu_(acc[mt][nt][0] + bb.x));
                o.y = tf32f_(silu_(acc[mt][nt][1] + bb.y));
                *(float2*)(g_uvqk + (size_t)r * 1024 + c) = o;
            }
            if (r + 8 < L) {
                float2 o;
                o.x = tf32f_(silu_(acc[mt][nt][2] + bb.x));
                o.y = tf32f_(silu_(acc[mt][nt][3] + bb.y));
                *(float2*)(g_uvqk + (size_t)(r + 8) * 1024 + c) = o;
            }
        }
}

// ---------------- GEMM2a: out = x + [u|x] @ Wout[0:768] (independent of attention) ----------------
__global__ __launch_bounds__(256) void k_gemm2a_tc(const float* __restrict__ x,
                                                   const float* __restrict__ Wout, int L,
                                                   float* __restrict__ out) {
    extern __shared__ unsigned smu[];
    unsigned* AsB = smu;
    unsigned* BsB = smu + 2 * AS_WORDS;
    int tid = threadIdx.x, lane = tid & 31, wid = tid >> 5;
    int wm = wid >> 2, wn = wid & 3;
    int l4 = lane >> 2, l3 = lane & 3;
    int row0 = blockIdx.y * 128, col0 = blockIdx.x * 128;

    float acc[4][4][4];
#pragma unroll
    for (int i = 0; i < 4; i++)
#pragma unroll
        for (int j = 0; j < 4; j++)
#pragma unroll
            for (int q = 0; q < 4; q++) acc[i][j][q] = 0.f;

    int ar_r = tid >> 3, ar_c = (tid & 7) * 4;
    int br_r = tid >> 5, br_c = (tid & 31) * 4;

    auto prefetch = [&](int k0, int st) {
        unsigned* As = AsB + st * AS_WORDS;
        unsigned* Bs = BsB + st * BS_WORDS;
        int j = k0 + ar_c;
        const float* base;
        int pitch;
        if (j < 256) { base = g_uvqk + j; pitch = 1024; }
        else { base = x + (j - 256); pitch = 512; }
#pragma unroll
        for (int p = 0; p < 4; p++) {
            int gr = min(row0 + ar_r + p * 32, L - 1);
            cpa16(&As[(ar_r + p * 32) * AS_PITCH + ar_c], base + (size_t)gr * pitch);
            cpa16(&Bs[(br_r + p * 8) * BS_PITCH + br_c],
                  Wout + (size_t)(k0 + br_r + p * 8) * 512 + col0 + br_c);
        }
        CP_COMMIT;
    };

    prefetch(0, 0);
    CP_WAIT0;
    __syncthreads();
    int cur = 0;
    for (int k0 = 0; k0 < 768; k0 += 32) {
        if (k0 + 32 < 768) prefetch(k0 + 32, cur ^ 1);
        {
            unsigned* As = AsB + cur * AS_WORDS;
            unsigned* Bs = BsB + cur * BS_WORDS;
            GEMM_COMPUTE();
        }
        if (k0 + 32 < 768) {
            CP_WAIT0;
            __syncthreads();
            cur ^= 1;
        }
    }

#pragma unroll
    for (int mt = 0; mt < 4; mt++)
#pragma unroll
        for (int nt = 0; nt < 4; nt++) {
            int r = row0 + wm * 64 + mt * 16 + l4;
            int c = col0 + wn * 32 + nt * 8 + l3 * 2;
            if (r < L) {
                float2 xv = *(const float2*)(x + (size_t)r * 512 + c);
                float2 o;
                o.x = xv.x + acc[mt][nt][0];
                o.y = xv.y + acc[mt][nt][1];
                *(float2*)(out + (size_t)r * 512 + c) = o;
            }
            if (r + 8 < L) {
                float2 xv = *(const float2*)(x + (size_t)(r + 8) * 512 + c);
                float2 o;
                o.x = xv.x + acc[mt][nt][2];
                o.y = xv.y + acc[mt][nt][3];
                *(float2*)(out + (size_t)(r + 8) * 512 + c) = o;
            }
        }
}

// ---------------- GEMM2b: out += g_y @ Wout[768:1024] ----------------
__global__ __launch_bounds__(256) void k_gemm2b_tc(const float* __restrict__ Wout, int L,
                                                   float* __restrict__ out) {
    extern __shared__ unsigned smu[];
    unsigned* AsB = smu;
    unsigned* BsB = smu + 2 * AS_WORDS;
    int tid = threadIdx.x, lane = tid & 31, wid = tid >> 5;
    int wm = wid >> 2, wn = wid & 3;
    int l4 = lane >> 2, l3 = lane & 3;
    int row0 = blockIdx.y * 128, col0 = blockIdx.x * 128;

    float acc[4][4][4];
#pragma unroll
    for (int i = 0; i < 4; i++)
#pragma unroll
        for (int j = 0; j < 4; j++)
#pragma unroll
            for (int q = 0; q < 4; q++) acc[i][j][q] = 0.f;

    int ar_r = tid >> 3, ar_c = (tid & 7) * 4;
    int br_r = tid >> 5, br_c = (tid & 31) * 4;

    auto prefetch = [&](int k0, int st) {
        unsigned* As = AsB + st * AS_WORDS;
        unsigned* Bs = BsB + st * BS_WORDS;
#pragma unroll
        for (int p = 0; p < 4; p++) {
            int gr = min(row0 + ar_r + p * 32, L - 1);
            cpa16(&As[(ar_r + p * 32) * AS_PITCH + ar_c],
                  g_y + (size_t)gr * 256 + k0 + ar_c);
            cpa16(&Bs[(br_r + p * 8) * BS_PITCH + br_c],
                  Wout + (size_t)(768 + k0 + br_r + p * 8) * 512 + col0 + br_c);
        }
        CP_COMMIT;
    };

    prefetch(0, 0);
    CP_WAIT0;
    __syncthreads();
    int cur = 0;
    for (int k0 = 0; k0 < 256; k0 += 32) {
        if (k0 + 32 < 256) prefetch(k0 + 32, cur ^ 1);
        {
            unsigned* As = AsB + cur * AS_WORDS;
            unsigned* Bs = BsB + cur * BS_WORDS;
            GEMM_COMPUTE();
        }
        if (k0 + 32 < 256) {
            CP_WAIT0;
            __syncthreads();
            cur ^= 1;
        }
    }

#pragma unroll
    for (int mt = 0; mt < 4; mt++)
#pragma unroll
        for (int nt = 0; nt < 4; nt++) {
            int r = row0 + wm * 64 + mt * 16 + l4;
            int c = col0 + wn * 32 + nt * 8 + l3 * 2;
            if (r < L) {
                float* op = out + (size_t)r * 512 + c;
                float2 ov = *(const float2*)op;
                ov.x += acc[mt][nt][0];
                ov.y += acc[mt][nt][1];
                *(float2*)op = ov;
            }
            if (r + 8 < L) {
                float* op = out + (size_t)(r + 8) * 512 + c;
                float2 ov = *(const float2*)op;
                ov.x += acc[mt][nt][2];
                ov.y += acc[mt][nt][3];
                *(float2*)op = ov;
            }
        }
}

// ---------------- attention (tensor core tf32, cp.async double-buffered K/V) ----------------
#define ATT_QS 0
#define ATT_KS 4352
#define ATT_KS_W 4352
#define ATT_VS 13056
#define ATT_VS_W 4608
#define ATT_SMEM ((13056 + 2 * 4608) * 4)

__global__ __launch_bounds__(256) void k_attn_tc(const int* __restrict__ lengths,
                                                 const int* __restrict__ offsets,
                                                 const int* __restrict__ ntargets,
                                                 const int* __restrict__ msl, int TPB) {
    extern __shared__ unsigned smu[];
    unsigned(*QSs)[68] = (unsigned(*)[68])(smu + ATT_QS);
    float(*Ss)[68] = (float(*)[68])(smu + ATT_QS);  // alias: Q consumed before S written

    int h = blockIdx.y;
    int b = blockIdx.x / TPB;
    int t = TPB - 1 - (blockIdx.x % TPB);  // long blocks launch first
    int len = lengths[b];
    int q0 = t * 64;
    if (q0 >= len) return;
    int off = offsets[b];
    int lim = len - ntargets[b];
    float invN = 1.0f / (float)msl[0];
    float c1 = 0.125f * invN;

    int tid = threadIdx.x, lane = tid & 31, wid = tid >> 5;
    int wm = wid >> 1, wn = wid & 1;
    int l4 = lane >> 2, l3 = lane & 3;
    int lr = tid >> 2, lc0 = (tid & 3) * 16;

    const uint4 zero4 = make_uint4(0u, 0u, 0u, 0u);

    auto prefetchKV = [&](int m0, int st) {
        int m = m0 + lr;
        bool ok = m < len;
        const float* kp =
            g_uvqk + (size_t)(off + min(m, len - 1)) * 1024 + 768 + h * 64 + lc0;
        const float* vp = kp - 512;
        unsigned* Kst = smu + ATT_KS + st * ATT_KS_W;
        unsigned* Vst = smu + ATT_VS + st * ATT_VS_W;
#pragma unroll
        for (int i = 0; i < 4; i++) {
            cpa16z(&Kst[lr * 68 + lc0 + i * 4], kp + i * 4, ok);
            cpa16z(&Vst[lr * 72 + lc0 + i * 4], vp + i * 4, ok);
        }
        CP_COMMIT;
    };

    prefetchKV(0, 0);
    {
        int n = q0 + lr;
        const uint4* qp = (const uint4*)(g_uvqk + (size_t)(off + min(n, len - 1)) * 1024 +
                                         512 + h * 64 + lc0);
        bool ok = n < len;
#pragma unroll
        for (int i = 0; i < 4; i++)
            *(uint4*)&QSs[lr][lc0 + i * 4] = ok ? qp[i] : zero4;
    }
    __syncthreads();

    unsigned qf[8][4];
#pragma unroll
    for (int ks = 0; ks < 8; ks++) {
        qf[ks][0] = QSs[wm * 16 + l4][ks * 8 + l3];
        qf[ks][1] = QSs[wm * 16 + l4 + 8][ks * 8 + l3];
        qf[ks][2] = QSs[wm * 16 + l4][ks * 8 + l3 + 4];
        qf[ks][3] = QSs[wm * 16 + l4 + 8][ks * 8 + l3 + 4];
    }

    float oacc[4][4];
#pragma unroll
    for (int i = 0; i < 4; i++)
#pragma unroll
        for (int j = 0; j < 4; j++) oacc[i][j] = 0.f;

    int nIter = q0 / 64 + 1;
    int cur = 0;
    for (int it = 0; it < nIter; it++) {
        int m0 = it * 64;
        CP_WAIT0;
        __syncthreads();
        if (it + 1 < nIter) prefetchKV(m0 + 64, cur ^ 1);

        const unsigned* Kst = smu + ATT_KS + cur * ATT_KS_W;
        const unsigned* Vst = smu + ATT_VS + cur * ATT_VS_W;

        float sacc[4][4];
#pragma unroll
        for (int i = 0; i < 4; i++)
#pragma unroll
            for (int j = 0; j < 4; j++) sacc[i][j] = 0.f;
#pragma unroll
        for (int ks = 0; ks < 8; ks++) {
            unsigned b0[4], b1[4];
#pragma unroll
            for (int nt = 0; nt < 4; nt++) {
                int mr = wn * 32 + nt * 8 + l4;
                b0[nt] = Kst[mr * 68 + ks * 8 + l3];
                b1[nt] = Kst[mr * 68 + ks * 8 + l3 + 4];
            }
#pragma unroll
            for (int nt = 0; nt < 4; nt++)
                mma8(sacc[nt], qf[ks][0], qf[ks][1], qf[ks][2], qf[ks][3], b0[nt], b1[nt]);
        }

        bool easy = (m0 + 64 <= q0) && (q0 + 64 <= lim);
        if (easy) {
#pragma unroll
            for (int nt = 0; nt < 4; nt++) {
#pragma unroll
                for (int q = 0; q < 4; q++) {
                    float s = sacc[nt][q];
                    float tg = tanh_(s * 0.0625f);
                    sacc[nt][q] = (s * c1) * fmaf(0.5f, tg, 0.5f);
                }
                int sr = wm * 16 + l4;
                int sc = wn * 32 + nt * 8 + 2 * l3;
                *(float2*)&Ss[sr][sc] = make_float2(sacc[nt][0], sacc[nt][1]);
                *(float2*)&Ss[sr + 8][sc] = make_float2(sacc[nt][2], sacc[nt][3]);
            }
        } else {
            int n_lo = q0 + wm * 16 + l4;
            int n_hi = n_lo + 8;
            int idn_lo = min(n_lo, lim), idn_hi = min(n_hi, lim);
            bool nok_lo = n_lo < len, nok_hi = n_hi < len;
#pragma unroll
            for (int nt = 0; nt < 4; nt++) {
                int m_ = m0 + wn * 32 + nt * 8 + 2 * l3;
#pragma unroll
                for (int jj = 0; jj < 2; jj++) {
                    int m = m_ + jj;
                    int idm = min(m, lim);
                    bool mok = m < len;
                    float s0 = sacc[nt][jj];
                    float w0 = (s0 * c1) * fmaf(0.5f, tanh_(s0 * 0.0625f), 0.5f);
                    bool ok0 = mok && nok_lo && ((idn_lo > idm) || (n_lo == m));
                    sacc[nt][jj] = ok0 ? w0 : 0.f;
                    float s1 = sacc[nt][jj + 2];
                    float w1 = (s1 * c1) * fmaf(0.5f, tanh_(s1 * 0.0625f), 0.5f);
                    bool ok1 = mok && nok_hi && ((idn_hi > idm) || (n_hi == m));
                    sacc[nt][jj + 2] = ok1 ? w1 : 0.f;
                }
                int sr = wm * 16 + l4;
                int sc = wn * 32 + nt * 8 + 2 * l3;
                *(float2*)&Ss[sr][sc] = make_float2(sacc[nt][0], sacc[nt][1]);
                *(float2*)&Ss[sr + 8][sc] = make_float2(sacc[nt][2], sacc[nt][3]);
            }
        }
        __syncthreads();

#pragma unroll
        for (int km = 0; km < 8; km++) {
            unsigned a0 = __float_as_uint(Ss[wm * 16 + l4][km * 8 + l3]);
            unsigned a1 = __float_as_uint(Ss[wm * 16 + l4 + 8][km * 8 + l3]);
            unsigned a2 = __float_as_uint(Ss[wm * 16 + l4][km * 8 + l3 + 4]);
            unsigned a3 = __float_as_uint(Ss[wm * 16 + l4 + 8][km * 8 + l3 + 4]);
#pragma unroll
            for (int nt = 0; nt < 4; nt++) {
                unsigned b0 = Vst[(km * 8 + l3) * 72 + wn * 32 + nt * 8 + l4];
                unsigned b1 = Vst[(km * 8 + l3 + 4) * 72 + wn * 32 + nt * 8 + l4];
                mma8(oacc[nt], a0, a1, a2, a3, b0, b1);
            }
        }
        cur ^= 1;
    }

#pragma unroll
    for (int nt = 0; nt < 4; nt++) {
        int col = h * 64 + wn * 32 + nt * 8 + 2 * l3;
        int n = q0 + wm * 16 + l4;
        if (n < len)
            *(float2*)&g_attn[(size_t)(off + n) * 256 + col] =
                make_float2(oacc[nt][0], oacc[nt][1]);
        if (n + 8 < len)
            *(float2*)&g_attn[(size_t)(off + n + 8) * 256 + col] =
                make_float2(oacc[nt][2], oacc[nt][3]);
    }
}

extern "C" void kernel_launch(void* const* d_in, const int* in_sizes, int n_in,
                              void* d_out, int out_size) {
    const float* x = (const float*)d_in[0];
    const int* xl = (const int*)d_in[1];
    const int* xo = (const int*)d_in[2];
    const int* msl = (const int*)d_in[3];
    const int* nt = (const int*)d_in[4];
    const float* Wu = (const float*)d_in[5];
    const float* bu = (const float*)d_in[6];
    const float* inw = (const float*)d_in[7];
    const float* inb = (const float*)d_in[8];
    const float* onw = (const float*)d_in[9];
    const float* onb = (const float*)d_in[10];
    const float* Wo = (const float*)d_in[11];
    float* out = (float*)d_out;

    int L = in_sizes[0] / 512;
    int B = in_sizes[1];

    static cudaStream_t s2 = nullptr;
    static cudaEvent_t evFork = nullptr, evJoin = nullptr;
    static bool init_done = false;
    if (!init_done) {
        cudaFuncSetAttribute(k_attn_tc, cudaFuncAttributeMaxDynamicSharedMemorySize,
                             ATT_SMEM);
        cudaFuncSetAttribute(k_gemm1_tc, cudaFuncAttributeMaxDynamicSharedMemorySize,
                             GEMM_SMEM);
        cudaFuncSetAttribute(k_gemm2a_tc, cudaFuncAttributeMaxDynamicSharedMemorySize,
                             GEMM_SMEM);
        cudaFuncSetAttribute(k_gemm2b_tc, cudaFuncAttributeMaxDynamicSharedMemorySize,
                             GEMM_SMEM);
        cudaStreamCreateWithFlags(&s2, cudaStreamNonBlocking);
        cudaEventCreateWithFlags(&evFork, cudaEventDisableTiming);
        cudaEventCreateWithFlags(&evJoin, cudaEventDisableTiming);
        init_done = true;
    }

    k_ln_in<<<(L + 7) / 8, 256>>>(x, inw, inb, L);

    dim3 g1(1024 / 128, (L + 127) / 128);
    k_gemm1_tc<<<g1, 256, GEMM_SMEM>>>(Wu, bu, L);

    // fork: gemm2a (depends only on gemm1) runs concurrently with attention + ln_out
    cudaEventRecord(evFork, 0);
    cudaStreamWaitEvent(s2, evFork, 0);
    dim3 g2(512 / 128, (L + 127) / 128);
    k_gemm2a_tc<<<g2, 256, GEMM_SMEM, s2>>>(x, Wo, L, out);
    cudaEventRecord(evJoin, s2);

    int TPB = (L + 63) / 64;
    dim3 ga(B * TPB, HH);
    k_attn_tc<<<ga, 256, ATT_SMEM>>>(xl, xo, nt, msl, TPB);

    k_ln_out<<<(L + 7) / 8, 256>>>(onw, onb, L);

    // join, then the y-dependent tail of GEMM2
    cudaStreamWaitEvent(0, evJoin, 0);
    k_gemm2b_tc<<<g2, 256, GEMM_SMEM>>>(Wo, L, out);
}